// round 15
// baseline (speedup 1.0000x reference)
#include <cuda_runtime.h>
#include <cstdint>
#include <cstddef>

#define NUM_HEADS 8
#define NTOK 50
#define HEADDIM 32
#define NWIN 2048
#define CDIM 256
#define MTOT (NWIN * NTOK)  // 102400

// Scratch (allocation-free rule: __device__ globals)
// Frag-major images (see index formulas in kernels):
//   A-image (x / attn-out): [mtile 800][kslab 16][wm 2][tmf 4][st 2][lane 32] uint4
//   B-image (weights):      [ntile]    [kslab 16][wn 2][tnf 8][st 2][lane 32] uint2
__device__ float g_qkv[3ULL * NWIN * NUM_HEADS * NTOK * HEADDIM];  // [which][b][h][t][d]
__device__ float g_xs[(size_t)MTOT * CDIM];
__device__ float g_atts[(size_t)MTOT * CDIM];
__device__ float g_wq[768 * 256];
__device__ float g_wp[256 * 256];
__device__ float g_bias[NUM_HEADS * NTOK * NTOK];

__device__ __forceinline__ uint32_t f2tf32(float f) {
    uint32_t r;
    asm("cvt.rna.tf32.f32 %0, %1;" : "=r"(r) : "f"(f));
    return r;
}
__device__ __forceinline__ float tfr(float f) { return __uint_as_float(f2tf32(f)); }

__device__ __forceinline__ uint32_t smem_u32(const void* p) {
    uint32_t a;
    asm("{ .reg .u64 t; cvta.to.shared.u64 t, %1; cvt.u32.u64 %0, t; }" : "=r"(a) : "l"(p));
    return a;
}

__device__ __forceinline__ void mma_tf32(float d[4],
                                         uint32_t a0, uint32_t a1, uint32_t a2, uint32_t a3,
                                         uint32_t b0, uint32_t b1) {
    asm volatile(
        "mma.sync.aligned.m16n8k8.row.col.f32.tf32.tf32.f32 "
        "{%0,%1,%2,%3}, {%4,%5,%6,%7}, {%8,%9}, {%0,%1,%2,%3};\n"
        : "+f"(d[0]), "+f"(d[1]), "+f"(d[2]), "+f"(d[3])
        : "r"(a0), "r"(a1), "r"(a2), "r"(a3), "r"(b0), "r"(b1));
}
__device__ __forceinline__ void mma_tf32f(float d[4],
                                          float a0, float a1, float a2, float a3,
                                          float b0, float b1) {
    mma_tf32(d, __float_as_uint(a0), __float_as_uint(a1), __float_as_uint(a2),
             __float_as_uint(a3), __float_as_uint(b0), __float_as_uint(b1));
}

__device__ __forceinline__ void cp16(uint32_t dst, const void* src) {
    asm volatile("cp.async.cg.shared.global [%0], [%1], 16;" :: "r"(dst), "l"(src));
}
#define CP_COMMIT() asm volatile("cp.async.commit_group;")
template <int N>
__device__ __forceinline__ void cp_wait() {
    asm volatile("cp.async.wait_group %0;" :: "n"(N));
}

// A-image float index for logical (m, k), m in [0,MTOT), k in [0,256)
__device__ __forceinline__ size_t aimg_idx(int m, int k) {
    int mt = m >> 7, ks = k >> 4;
    int wm = (m >> 6) & 1, tmf = (m >> 4) & 3, st = (k >> 3) & 1;
    int lane = (m & 7) * 4 + (k & 3);
    int e = ((k >> 2) & 1) * 2 + ((m >> 3) & 1);
    return (((((size_t)mt * 16 + ks) * 2 + wm) * 4 + tmf) * 2 + st) * 128 + lane * 4 + e;
}

// ---------------------------------------------------------------------------
// Kernel 0: expand relative-position bias table -> [8][50][50], zero row/col 0
// ---------------------------------------------------------------------------
__global__ void bias_expand_kernel(const float* __restrict__ bt, const int* __restrict__ ridx) {
    int i = blockIdx.x * 256 + threadIdx.x;
    if (i >= NUM_HEADS * NTOK * NTOK) return;
    int h = i / (NTOK * NTOK);
    int rem = i - h * NTOK * NTOK;
    int r = rem / NTOK;
    int c = rem - r * NTOK;
    float v = 0.f;
    if (r > 0 && c > 0) {
        int idx = ridx[(r - 1) * 49 + (c - 1)];
        v = bt[idx * NUM_HEADS + h];
    }
    g_bias[i] = v;
}

// ---------------------------------------------------------------------------
// xconv: build frag-major A-image of x. One thread = one uint4 fragment.
// idx = ((((mt*16+ks)*2+wm)*4+tmf)*2+st)*32 + lane
// ---------------------------------------------------------------------------
__global__ void xconv_kernel(const float* __restrict__ x) {
    size_t idx = (size_t)blockIdx.x * 256 + threadIdx.x;
    if (idx >= (size_t)MTOT * 64) return;
    int lane = (int)(idx & 31);
    int st = (int)(idx >> 5) & 1;
    int tmf = (int)(idx >> 6) & 3;
    int wm = (int)(idx >> 8) & 1;
    int ks = (int)(idx >> 9) & 15;
    int mt = (int)(idx >> 13);
    int r = mt * 128 + wm * 64 + tmf * 16 + (lane >> 2);
    int k = ks * 16 + st * 8 + (lane & 3);
    const float* xr0 = x + (size_t)r * 256;
    const float* xr1 = xr0 + 8 * 256;
    uint4 o = make_uint4(f2tf32(xr0[k]), f2tf32(xr1[k]), f2tf32(xr0[k + 4]), f2tf32(xr1[k + 4]));
    *(uint4*)(g_xs + idx * 4) = o;
}

// ---------------------------------------------------------------------------
// wconv: build frag-major B-image. One thread = one uint2 fragment.
// idx = ((((nt*16+ks)*2+wn)*8+tnf)*2+st)*32 + lane
// ---------------------------------------------------------------------------
__global__ void wconv_kernel(const float* __restrict__ w, int which, int total) {
    int idx = blockIdx.x * 256 + threadIdx.x;
    if (idx >= total) return;
    int lane = idx & 31;
    int st = (idx >> 5) & 1;
    int tnf = (idx >> 6) & 7;
    int wn = (idx >> 9) & 1;
    int ks = (idx >> 10) & 15;
    int nt = idx >> 14;
    int n = nt * 128 + wn * 64 + tnf * 8 + (lane >> 2);
    int k = ks * 16 + st * 8 + (lane & 3);
    float* base = which ? g_wp : g_wq;
    *(uint2*)(base + (size_t)idx * 2) =
        make_uint2(f2tf32(w[(size_t)n * 256 + k]), f2tf32(w[(size_t)n * 256 + k + 4]));
}

// ---------------------------------------------------------------------------
// GEMM: C[M,N] = A[M,256] @ W[N,256]^T + bias. Frag-major tf32 images.
// BM=BN=128, 4 warps (2m x 2n), warp tile 64x64. 16 k16-stages, 3-stage
// cp.async pipeline, 48KB static smem. epi0: QKV scatter; epi1: out.
// ---------------------------------------------------------------------------
__global__ __launch_bounds__(128) void gemm_fm_kernel(
    const float* __restrict__ bias, float* __restrict__ out, int epi)
{
    const float* Aimg = epi ? g_atts : g_xs;
    const float* Bimg = epi ? g_wp : g_wq;

    __shared__ __align__(16) float sm[3][4096];  // stage: A 2048 | B 2048; 48KB

    const int tid = threadIdx.x;
    const int lane = tid & 31;
    const int warp = tid >> 5;
    const int wm = warp >> 1, wn = warp & 1;
    const int bm = blockIdx.y, bn = blockIdx.x;

    const float* Abase = Aimg + (size_t)bm * 32768;
    const float* Bbase = Bimg + (size_t)bn * 32768;
    const uint32_t sbuf[3] = { smem_u32(sm[0]), smem_u32(sm[1]), smem_u32(sm[2]) };

    float acc[4][8][4];
#pragma unroll
    for (int i = 0; i < 4; i++)
#pragma unroll
        for (int j = 0; j < 8; j++)
#pragma unroll
            for (int r = 0; r < 4; r++) acc[i][j][r] = 0.f;

    auto issue = [&](int s, int buf) {
        const float* As = Abase + s * 2048;
        const float* Bs = Bbase + s * 2048;
        uint32_t sa = sbuf[buf];
#pragma unroll
        for (int c = 0; c < 4; c++)
            cp16(sa + (uint32_t)(c * 128 + tid) * 16u, As + (c * 128 + tid) * 4);
#pragma unroll
        for (int c = 0; c < 4; c++)
            cp16(sa + 8192u + (uint32_t)(c * 128 + tid) * 16u, Bs + (c * 128 + tid) * 4);
        CP_COMMIT();
    };

    issue(0, 0);
    issue(1, 1);
    issue(2, 2);

#pragma unroll
    for (int s = 0; s < 16; s++) {
        if (s < 14) cp_wait<2>();
        else if (s == 14) cp_wait<1>();
        else cp_wait<0>();
        __syncthreads();
        const float* A = sm[s % 3];
        const float* B = A + 2048;

#pragma unroll
        for (int st = 0; st < 2; st++) {
            uint4 af[4];
#pragma unroll
            for (int tmf = 0; tmf < 4; tmf++)
                af[tmf] = *(const uint4*)&A[((wm * 4 + tmf) * 2 + st) * 128 + lane * 4];
            uint2 bf[8];
#pragma unroll
            for (int tnf = 0; tnf < 8; tnf++)
                bf[tnf] = *(const uint2*)&B[((wn * 8 + tnf) * 2 + st) * 64 + lane * 2];
#pragma unroll
            for (int tmf = 0; tmf < 4; tmf++)
#pragma unroll
                for (int tnf = 0; tnf < 8; tnf++)
                    mma_tf32(acc[tmf][tnf], af[tmf].x, af[tmf].y, af[tmf].z, af[tmf].w,
                             bf[tnf].x, bf[tnf].y);
        }
        __syncthreads();
        if (s + 3 < 16) issue(s + 3, s % 3);
    }

    const float scale = 0.17677669529663687f;  // 32^-0.5
#pragma unroll
    for (int tmf = 0; tmf < 4; tmf++)
#pragma unroll
        for (int tnf = 0; tnf < 8; tnf++) {
            int m_g = bm * 128 + wm * 64 + tmf * 16 + (lane >> 2);
            int n_g = bn * 128 + wn * 64 + tnf * 8 + 2 * (lane & 3);
#pragma unroll
            for (int hf = 0; hf < 2; hf++) {
                int mm = m_g + hf * 8;
                float v0 = acc[tmf][tnf][hf * 2 + 0] + __ldg(bias + n_g);
                float v1 = acc[tmf][tnf][hf * 2 + 1] + __ldg(bias + n_g + 1);
                if (epi == 0) {
                    int which = n_g >> 8;
                    int rcol = n_g & 255;
                    int h = rcol >> 5, d = rcol & 31;
                    if (which == 0) { v0 *= scale; v1 *= scale; }
                    int b = mm / NTOK;
                    int t = mm - b * NTOK;
                    size_t idx = ((size_t)which * NWIN * NUM_HEADS + (size_t)b * NUM_HEADS + h)
                                     * (NTOK * HEADDIM)
                                 + t * HEADDIM + d;
                    *(float2*)(g_qkv + idx) = make_float2(v0, v1);
                } else {
                    *(float2*)(out + (size_t)mm * CDIM + n_g) = make_float2(v0, v1);
                }
            }
        }
}

// ---------------------------------------------------------------------------
// Kernel 2: MMA attention per (window, head). 128 threads = 4 warps.
// (verified R14) Output now written into the frag-major A-image g_atts.
// ---------------------------------------------------------------------------
__global__ __launch_bounds__(128) void attn_kernel() {
    __shared__ __align__(16) float smem[11656];
    float* qh = smem;
    float* ql = smem + 2304;
    float* kh = smem + 4608;
    float* kl = smem + 6912;
    float* vt = smem + 9216;
    float* Ps = smem;  // aliases qh/ql after QK
    float* redmax = smem + 11392;
    float* redsum = smem + 11492;
    float* rinv = smem + 11592;

    const int bh = blockIdx.x;
    const int b = bh >> 3, h = bh & 7;
    const int tid = threadIdx.x;
    const int lane = tid & 31;
    const int warp = tid >> 5;

    const size_t strideWH = (size_t)NWIN * NUM_HEADS * NTOK * HEADDIM;
    const float* qg = g_qkv + ((size_t)b * NUM_HEADS + h) * (NTOK * HEADDIM);
    const float* kg = qg + strideWH;
    const float* vg = kg + strideWH;

    for (int i = tid; i < 32 * 14; i += 128) {
        int d = i / 14, c = 50 + (i % 14);
        vt[d * 68 + c] = 0.f;
    }
    for (int i = tid; i < 400; i += 128) {
        int r = i >> 3, c4 = (i & 7) * 4;
        float4 q = *(const float4*)(qg + i * 4);
        float4 k = *(const float4*)(kg + i * 4);
        float4 v = *(const float4*)(vg + i * 4);
        float4 qhi = make_float4(tfr(q.x), tfr(q.y), tfr(q.z), tfr(q.w));
        float4 khi = make_float4(tfr(k.x), tfr(k.y), tfr(k.z), tfr(k.w));
        *(float4*)&qh[r * 36 + c4] = qhi;
        *(float4*)&kh[r * 36 + c4] = khi;
        *(float4*)&ql[r * 36 + c4] =
            make_float4(tfr(q.x - qhi.x), tfr(q.y - qhi.y), tfr(q.z - qhi.z), tfr(q.w - qhi.w));
        *(float4*)&kl[r * 36 + c4] =
            make_float4(tfr(k.x - khi.x), tfr(k.y - khi.y), tfr(k.z - khi.z), tfr(k.w - khi.w));
        vt[(c4 + 0) * 68 + r] = tfr(v.x);
        vt[(c4 + 1) * 68 + r] = tfr(v.y);
        vt[(c4 + 2) * 68 + r] = tfr(v.z);
        vt[(c4 + 3) * 68 + r] = tfr(v.w);
    }
    __syncthreads();

    // QK: S = Q K^T via 3xTF32
    float sacc[8][4];
#pragma unroll
    for (int j = 0; j < 8; j++)
#pragma unroll
        for (int r = 0; r < 4; r++) sacc[j][r] = 0.f;

    const int fr = warp * 16 + (lane >> 2);
#pragma unroll
    for (int ks = 0; ks < 4; ks++) {
        const int kk = ks * 8 + (lane & 3);
        float ah0 = qh[fr * 36 + kk], ah1 = qh[(fr + 8) * 36 + kk];
        float ah2 = qh[fr * 36 + kk + 4], ah3 = qh[(fr + 8) * 36 + kk + 4];
        float al0 = ql[fr * 36 + kk], al1 = ql[(fr + 8) * 36 + kk];
        float al2 = ql[fr * 36 + kk + 4], al3 = ql[(fr + 8) * 36 + kk + 4];
#pragma unroll
        for (int tn = 0; tn < 8; tn++) {
            int n = tn * 8 + (lane >> 2);
            float bh0 = kh[n * 36 + kk], bh1 = kh[n * 36 + kk + 4];
            float bl0 = kl[n * 36 + kk], bl1 = kl[n * 36 + kk + 4];
            mma_tf32f(sacc[tn], ah0, ah1, ah2, ah3, bh0, bh1);
            mma_tf32f(sacc[tn], ah0, ah1, ah2, ah3, bl0, bl1);
            mma_tf32f(sacc[tn], al0, al1, al2, al3, bh0, bh1);
        }
    }
    __syncthreads();  // Ps aliases qh/ql

#pragma unroll
    for (int tn = 0; tn < 8; tn++) {
        int c = tn * 8 + 2 * (lane & 3);
        *(float2*)&Ps[fr * 68 + c] = make_float2(sacc[tn][0], sacc[tn][1]);
        *(float2*)&Ps[(fr + 8) * 68 + c] = make_float2(sacc[tn][2], sacc[tn][3]);
    }
    __syncthreads();

    const int r = tid >> 1;
    const int half = tid & 1;
    const float* bg = g_bias + h * (NTOK * NTOK);
    float sv[25];
    if (r < 50) {
        const int cbase = half * 25;
        float smax = -1e30f;
#pragma unroll
        for (int c = 0; c < 25; c++) {
            float a = Ps[r * 68 + cbase + c] + __ldg(bg + r * 50 + cbase + c);
            sv[c] = a;
            smax = fmaxf(smax, a);
        }
        redmax[r * 2 + half] = smax;
    }
    __syncthreads();
    if (r < 50) {
        float m = fmaxf(redmax[r * 2], redmax[r * 2 + 1]);
        const int cbase = half * 25;
        float s = 0.f;
#pragma unroll
        for (int c = 0; c < 25; c++) {
            float e = tfr(__expf(sv[c] - m));
            Ps[r * 68 + cbase + c] = e;
            s += e;
        }
        redsum[r * 2 + half] = s;
#pragma unroll
        for (int c = 0; c < 7; c++) Ps[r * 68 + 50 + half * 7 + c] = 0.f;
    }
    __syncthreads();
    if (tid < 50) rinv[tid] = 1.f / (redsum[tid * 2] + redsum[tid * 2 + 1]);
    __syncthreads();

    float oacc[4][4];
#pragma unroll
    for (int j = 0; j < 4; j++)
#pragma unroll
        for (int t = 0; t < 4; t++) oacc[j][t] = 0.f;
#pragma unroll
    for (int ks = 0; ks < 8; ks++) {
        const int kk = ks * 8 + (lane & 3);
        float a0 = Ps[fr * 68 + kk], a1 = Ps[(fr + 8) * 68 + kk];
        float a2 = Ps[fr * 68 + kk + 4], a3 = Ps[(fr + 8) * 68 + kk + 4];
#pragma unroll
        for (int tn = 0; tn < 4; tn++) {
            int n = tn * 8 + (lane >> 2);
            float b0 = vt[n * 68 + kk], b1 = vt[n * 68 + kk + 4];
            mma_tf32f(oacc[tn], a0, a1, a2, a3, b0, b1);
        }
    }

    // output: normalize, tf32-round, scatter into frag-major A-image
#pragma unroll
    for (int tn = 0; tn < 4; tn++) {
#pragma unroll
        for (int hf = 0; hf < 2; hf++) {
            int row = fr + hf * 8;
            if (row < 50) {
                float rv = rinv[row];
                float v0 = oacc[tn][hf * 2 + 0] * rv;
                float v1 = oacc[tn][hf * 2 + 1] * rv;
                int m = b * NTOK + row;
                int kcol = h * 32 + tn * 8 + 2 * (lane & 3);
                g_atts[aimg_idx(m, kcol)] = tfr(v0);
                g_atts[aimg_idx(m, kcol + 1)] = tfr(v1);
            }
        }
    }
}

// ---------------------------------------------------------------------------
extern "C" void kernel_launch(void* const* d_in, const int* in_sizes, int n_in,
                              void* d_out, int out_size) {
    const float* x = (const float*)d_in[0];
    const float* qkv_w = (const float*)d_in[1];
    const float* qkv_b = (const float*)d_in[2];
    const float* proj_w = (const float*)d_in[3];
    const float* proj_b = (const float*)d_in[4];
    const float* bias_table = (const float*)d_in[5];
    const int* rel_idx = (const int*)d_in[6];
    float* out = (float*)d_out;

    (void)in_sizes; (void)n_in; (void)out_size;

    bias_expand_kernel<<<(NUM_HEADS * NTOK * NTOK + 255) / 256, 256>>>(bias_table, rel_idx);
    wconv_kernel<<<(768 * 128 / 256), 256>>>(qkv_w, 0, 768 * 128);   // 98304 uint2
    wconv_kernel<<<(256 * 128 / 256), 256>>>(proj_w, 1, 256 * 128);  // 32768 uint2
    xconv_kernel<<<(int)(((size_t)MTOT * 64) / 256), 256>>>(x);
    // QKV: M tiles (128 rows) = 800, N tiles (128 cols) = 6
    gemm_fm_kernel<<<dim3(6, 800), 128>>>(qkv_b, nullptr, 0);
    attn_kernel<<<NWIN * NUM_HEADS, 128>>>();
    // proj: N tiles = 2
    gemm_fm_kernel<<<dim3(2, 800), 128>>>(proj_b, out, 1);
}